// round 14
// baseline (speedup 1.0000x reference)
#include <cuda_runtime.h>
#include <cuda_bf16.h>
#include <stdint.h>

// ---------------- problem constants ----------------
#define BATCH   16384
#define QS      1204
#define FD      7
#define ROWLEN  (QS*FD)            // 8428 floats
#define ROW4    (ROWLEN/4)         // 2107
#define FK      600
#define RPC     64                 // rows per MLP CTA
#define NCTA    (BATCH/RPC)        // 256
#define NCH     19                 // 32-wide k-chunks in GEMM1 (608 = 19*32, k>=600 zero)
#define NCHT    27                 // + 4 w1 + 4 w2 chunks streamed after
#define KP      608                // padded K for GEMM1
#define FROWS   2                  // batch rows per feat CTA
#define FGRID   (BATCH/FROWS)      // 8192

// per-(blk,chunk) feat block: [Ahi 4KB | Alo 4KB], granule-interleaved
#define ACHB    8192
#define FBLKB   (NCH*ACHB)
// per weight chunk block: [Bhi 8KB | Blo 8KB], granule-interleaved
#define WCHB    16384

// ---------------- mlp smem layout (bytes) ----------------
#define SLOTB    24576             // [Ahi 4K|Alo 4K|Bhi 8K|Blo 8K]
#define OFF_RING 0                 // 49152
#define OFF_H0   49152             // [hi 16K|lo 16K] granule-interleaved
#define OFF_T1   81920             // same, 32KB
#define SMEM_TOTAL 114688
// overlays (after GEMM3):
#define OFF_F1   0                 // fp32 64x133 = 34048 (over ring)
#define OFF_WB   OFF_H0            // fp32 128x32 = 16384
#define OFF_F2   OFF_T1            // fp32 64x36  = 9216
#define F1ST     133

// feat kernel dynamic smem: 2 rows of x + 2 rows of s
#define FSMEM   ((2*ROWLEN + 2*QS) * 4)   // 77056

// ---------------- global scratch ----------------
__device__ __align__(128) char g_fA [(size_t)NCTA*FBLKB];
__device__ __align__(128) char g_wAt[NCH*WCHB];
__device__ __align__(128) char g_w1t[4*WCHB];
__device__ __align__(128) char g_w2t[4*WCHB];

// ---------------- helpers ----------------
__device__ __forceinline__ void split_bf16(float v, __nv_bfloat16& hi, __nv_bfloat16& lo) {
    hi = __float2bfloat16(v);
    lo = __float2bfloat16(v - __bfloat162float(hi));
}
__device__ __forceinline__ uint32_t pack_bf2(__nv_bfloat16 e0, __nv_bfloat16 e1) {
    return ((uint32_t)__bfloat16_as_ushort(e1) << 16) | (uint32_t)__bfloat16_as_ushort(e0);
}
__device__ __forceinline__ uint32_t smem_u32(const void* p) {
    return (uint32_t)__cvta_generic_to_shared(p);
}
__device__ __forceinline__ void mbar_init(uint32_t mbar, uint32_t cnt) {
    asm volatile("mbarrier.init.shared.b64 [%0], %1;" :: "r"(mbar), "r"(cnt) : "memory");
}
__device__ __forceinline__ void mbar_expect_tx(uint32_t mbar, uint32_t bytes) {
    asm volatile("mbarrier.arrive.expect_tx.shared.b64 _, [%0], %1;" :: "r"(mbar), "r"(bytes) : "memory");
}
__device__ __forceinline__ void mbar_wait(uint32_t mbar, uint32_t parity) {
    asm volatile(
        "{\n\t.reg .pred P;\n"
        "W%=:\n\t"
        "mbarrier.try_wait.parity.acquire.cta.shared::cta.b64 P, [%0], %1, 0x989680;\n\t"
        "@P bra D%=;\n\t"
        "bra W%=;\n"
        "D%=:\n\t}"
        :: "r"(mbar), "r"(parity) : "memory");
}
__device__ __forceinline__ void bulk_in(uint32_t dst, const void* src, uint32_t bytes, uint32_t mbar) {
    asm volatile(
        "cp.async.bulk.shared::cta.global.mbarrier::complete_tx::bytes [%0], [%1], %2, [%3];"
        :: "r"(dst), "l"(src), "r"(bytes), "r"(mbar) : "memory");
}
__device__ __forceinline__ void cp16(uint32_t dst, const void* src) {
    asm volatile("cp.async.cg.shared.global [%0], [%1], 16;" :: "r"(dst), "l"(src));
}
__device__ __forceinline__ void mma16816(float* c,
    uint32_t a0, uint32_t a1, uint32_t a2, uint32_t a3, uint32_t b0, uint32_t b1)
{
    asm volatile(
        "mma.sync.aligned.m16n8k16.row.col.f32.bf16.bf16.f32 "
        "{%0,%1,%2,%3}, {%4,%5,%6,%7}, {%8,%9}, {%0,%1,%2,%3};\n"
        : "+f"(c[0]), "+f"(c[1]), "+f"(c[2]), "+f"(c[3])
        : "r"(a0), "r"(a1), "r"(a2), "r"(a3), "r"(b0), "r"(b1));
}
__device__ __forceinline__ void ldsm_x4(uint32_t& r0, uint32_t& r1, uint32_t& r2, uint32_t& r3, uint32_t a) {
    asm volatile("ldmatrix.sync.aligned.m8n8.x4.shared.b16 {%0,%1,%2,%3}, [%4];"
                 : "=r"(r0), "=r"(r1), "=r"(r2), "=r"(r3) : "r"(a));
}
__device__ __forceinline__ void ldsm_x2(uint32_t& r0, uint32_t& r1, uint32_t a) {
    asm volatile("ldmatrix.sync.aligned.m8n8.x2.shared.b16 {%0,%1}, [%2];"
                 : "=r"(r0), "=r"(r1) : "r"(a));
}
__device__ __forceinline__ void zero_acc(float (&acc)[2][4][4]) {
    #pragma unroll
    for (int a = 0; a < 2; ++a)
        #pragma unroll
        for (int b = 0; b < 4; ++b)
            #pragma unroll
            for (int c = 0; c < 4; ++c) acc[a][b][c] = 0.f;
}
// store split pair into granule-interleaved 64-row tile (hi at base, lo at +16KB)
__device__ __forceinline__ void storeTile(char* base, int r, int col, float v0, float v1) {
    __nv_bfloat16 h0, l0, h1, l1;
    split_bf16(v0, h0, l0); split_bf16(v1, h1, l1);
    const int off = (col >> 3) * 1024 + r * 16 + ((2 * col) & 15);
    *(uint32_t*)(base + off)         = pack_bf2(h0, h1);
    *(uint32_t*)(base + off + 16384) = pack_bf2(l0, l1);
}

// GEMM1 chunk: A = 64-row chunk tile (granules of 16B, stride 1024), B = 128-row chunk (stride 2048)
__device__ __forceinline__ void gemm1_chunk(uint32_t slot,
    float (&acc)[2][4][4], int mb, int nb, int lane)
{
    const int lm  = lane & 15;
    const int lk  = lane >> 4;
    const int lnb = lane & 7;
    const int lbk = (lane >> 3) & 1;
    #pragma unroll
    for (int kk = 0; kk < 2; ++kk) {
        uint32_t ah[2][4], al[2][4];
        const uint32_t aoff = (uint32_t)(2 * kk + lk) * 1024;
        #pragma unroll
        for (int mt = 0; mt < 2; ++mt) {
            const uint32_t ra = (uint32_t)(mb + mt * 16 + lm) * 16;
            ldsm_x4(ah[mt][0], ah[mt][1], ah[mt][2], ah[mt][3], slot + aoff + ra);
            ldsm_x4(al[mt][0], al[mt][1], al[mt][2], al[mt][3], slot + 4096 + aoff + ra);
        }
        const uint32_t boff = (uint32_t)(2 * kk + lbk) * 2048;
        #pragma unroll
        for (int nt = 0; nt < 4; ++nt) {
            const uint32_t rb = (uint32_t)(nb + nt * 8 + lnb) * 16;
            uint32_t bh0, bh1, bl0, bl1;
            ldsm_x2(bh0, bh1, slot + 8192  + boff + rb);
            ldsm_x2(bl0, bl1, slot + 16384 + boff + rb);
            #pragma unroll
            for (int mt = 0; mt < 2; ++mt) {
                mma16816(acc[mt][nt], ah[mt][0], ah[mt][1], ah[mt][2], ah[mt][3], bh0, bh1);
                mma16816(acc[mt][nt], ah[mt][0], ah[mt][1], ah[mt][2], ah[mt][3], bl0, bl1);
                mma16816(acc[mt][nt], al[mt][0], al[mt][1], al[mt][2], al[mt][3], bh0, bh1);
            }
        }
    }
}

// GEMM2/3 chunk: A = H0/T1 tile (16 granule groups, stride 1024; hi at Abase, lo +16KB)
__device__ __forceinline__ void gemm23_chunk(uint32_t Abase, uint32_t slot,
    int kbase, float (&acc)[2][4][4], int mb, int nb, int lane)
{
    const int lm  = lane & 15;
    const int lk  = lane >> 4;
    const int lnb = lane & 7;
    const int lbk = (lane >> 3) & 1;
    #pragma unroll
    for (int kk = 0; kk < 2; ++kk) {
        uint32_t ah[2][4], al[2][4];
        const uint32_t aoff = (uint32_t)((kbase >> 3) + 2 * kk + lk) * 1024;
        #pragma unroll
        for (int mt = 0; mt < 2; ++mt) {
            const uint32_t ra = (uint32_t)(mb + mt * 16 + lm) * 16;
            ldsm_x4(ah[mt][0], ah[mt][1], ah[mt][2], ah[mt][3], Abase + aoff + ra);
            ldsm_x4(al[mt][0], al[mt][1], al[mt][2], al[mt][3], Abase + 16384 + aoff + ra);
        }
        const uint32_t boff = (uint32_t)(2 * kk + lbk) * 2048;
        #pragma unroll
        for (int nt = 0; nt < 4; ++nt) {
            const uint32_t rb = (uint32_t)(nb + nt * 8 + lnb) * 16;
            uint32_t bh0, bh1, bl0, bl1;
            ldsm_x2(bh0, bh1, slot + 8192  + boff + rb);
            ldsm_x2(bl0, bl1, slot + 16384 + boff + rb);
            #pragma unroll
            for (int mt = 0; mt < 2; ++mt) {
                mma16816(acc[mt][nt], ah[mt][0], ah[mt][1], ah[mt][2], ah[mt][3], bh0, bh1);
                mma16816(acc[mt][nt], ah[mt][0], ah[mt][1], ah[mt][2], ah[mt][3], bl0, bl1);
                mma16816(acc[mt][nt], al[mt][0], al[mt][1], al[mt][2], al[mt][3], bh0, bh1);
            }
        }
    }
}

// ---------------- kernel 1: feat x2 rows (+ merged presplit) ----------------
__global__ __launch_bounds__(256) void feat_presplit_kernel(
    const float* __restrict__ x,
    const float* __restrict__ w_step, const float* __restrict__ b_step,
    const float* __restrict__ wA, const float* __restrict__ w1,
    const float* __restrict__ w2)
{
    const int tid = threadIdx.x;

    if (blockIdx.x >= FGRID) {
        const int id = (blockIdx.x - FGRID) * 256 + tid;
        if (id < 77824) {                       // wA: 128 x 608 (k>=600 zero)
            const int n = id / KP, k = id % KP;
            const float v = (k < FK) ? __ldg(wA + n * FK + k) : 0.f;
            __nv_bfloat16 h, l; split_bf16(v, h, l);
            const int c = k >> 5, kl = k & 31;
            const int off = c * WCHB + (kl >> 3) * 2048 + n * 16 + (kl & 7) * 2;
            *(__nv_bfloat16*)(g_wAt + off)        = h;
            *(__nv_bfloat16*)(g_wAt + off + 8192) = l;
        } else if (id < 94208) {                // w1: 128 x 128
            const int t = id - 77824, n = t >> 7, k = t & 127;
            __nv_bfloat16 h, l; split_bf16(__ldg(w1 + n * 128 + k), h, l);
            const int c = k >> 5, kl = k & 31;
            const int off = c * WCHB + (kl >> 3) * 2048 + n * 16 + (kl & 7) * 2;
            *(__nv_bfloat16*)(g_w1t + off)        = h;
            *(__nv_bfloat16*)(g_w1t + off + 8192) = l;
        } else if (id < 110592) {               // w2
            const int t = id - 94208, n = t >> 7, k = t & 127;
            __nv_bfloat16 h, l; split_bf16(__ldg(w2 + n * 128 + k), h, l);
            const int c = k >> 5, kl = k & 31;
            const int off = c * WCHB + (kl >> 3) * 2048 + n * 16 + (kl & 7) * 2;
            *(__nv_bfloat16*)(g_w2t + off)        = h;
            *(__nv_bfloat16*)(g_w2t + off + 8192) = l;
        }
        return;
    }

    // ---- feat: 2 batch rows per block ----
    extern __shared__ float fsm[];
    float* sx = fsm;               // 2*ROWLEN
    float* ss = fsm + 2 * ROWLEN;  // 2*QS

    const int row0 = blockIdx.x * FROWS;
    const float4* src = (const float4*)(x + (size_t)row0 * ROWLEN);
    const uint32_t sxu = smem_u32(sx);
    for (int i = tid; i < 2 * ROW4; i += 256) cp16(sxu + i * 16, src + i);
    asm volatile("cp.async.commit_group;" ::: "memory");

    const float w0 = __ldg(w_step + 0), w1c = __ldg(w_step + 1), w2c = __ldg(w_step + 2),
                w3 = __ldg(w_step + 3), w4 = __ldg(w_step + 4), w5 = __ldg(w_step + 5),
                w6 = __ldg(w_step + 6), bs = __ldg(b_step);
    asm volatile("cp.async.wait_group 0;" ::: "memory");
    __syncthreads();

    for (int q = tid; q < 2 * QS; q += 256) {
        const int rs = (q >= QS) ? 1 : 0;
        const int qq = q - rs * QS;
        const float* p = sx + rs * ROWLEN + qq * FD;
        float v = fmaf(p[0], w0, fmaf(p[1], w1c, fmaf(p[2], w2c,
                  fmaf(p[3], w3, fmaf(p[4], w4, fmaf(p[5], w5, p[6] * w6))))));
        ss[q] = v + bs;
    }
    __syncthreads();

    const int blk = row0 >> 6;
    const int rl0 = row0 & 63;     // even
    char* fbase = g_fA + (size_t)blk * FBLKB;

    for (int t = tid; t < KP; t += 256) {        // 608 (row, feature-pair) tasks
        const int rs = t & 1;
        const int j0 = 2 * (t >> 1);
        const float* sr = ss + rs * QS;
        float v0 = 0.f, v1 = 0.f;
        if (j0 < FK) {
            {
                const int bl = j0 / 5, off = j0 % 5;
                const float* p = sr + off + bl * 10;
                float m = p[0];
                #pragma unroll
                for (int i = 1; i < 10; ++i) m = fmaxf(m, p[i]);
                v0 = m;
            }
            {
                const int j1 = j0 + 1;
                const int bl = j1 / 5, off = j1 % 5;
                const float* p = sr + off + bl * 10;
                float m = p[0];
                #pragma unroll
                for (int i = 1; i < 10; ++i) m = fmaxf(m, p[i]);
                v1 = m;
            }
        }
        __nv_bfloat16 h0, l0, h1, l1;
        split_bf16(v0, h0, l0);
        split_bf16(v1, h1, l1);
        const int c = j0 >> 5, kl = j0 & 31;
        const int off = c * ACHB + (kl >> 3) * 1024 + (rl0 + rs) * 16 + (kl & 7) * 2;
        *(uint32_t*)(fbase + off)        = pack_bf2(h0, h1);
        *(uint32_t*)(fbase + off + 4096) = pack_bf2(l0, l1);
    }
}

// ---------------- kernel 2: MLP, streamed ring, 2 CTA/SM ----------------
__global__ __launch_bounds__(256, 2) void mlp_kernel(
    const float* __restrict__ bA, const float* __restrict__ b1,
    const float* __restrict__ b2, const float* __restrict__ bB,
    const float* __restrict__ wB, const float* __restrict__ wC,
    const float* __restrict__ bC, float* __restrict__ out)
{
    extern __shared__ __align__(16) char smem[];
    __shared__ __align__(8) unsigned long long s_mb[2];

    const int tid  = threadIdx.x;
    const int wid  = tid >> 5;
    const int lane = tid & 31;
    const int g    = lane >> 2;
    const int tg   = lane & 3;
    const int mb   = (wid & 1) * 32;
    const int nb   = (wid >> 1) * 32;
    const int row0 = blockIdx.x * RPC;
    const uint32_t smb = smem_u32(smem);

    if (tid == 0) {
        mbar_init(smem_u32(&s_mb[0]), 1);
        mbar_init(smem_u32(&s_mb[1]), 1);
    }
    __syncthreads();

    auto fetch = [&](int cnt) {
        const int s = cnt & 1;
        const uint32_t m = smem_u32(&s_mb[s]);
        const uint32_t slot = smb + OFF_RING + s * SLOTB;
        if (cnt < NCH) {
            mbar_expect_tx(m, ACHB + WCHB);
            bulk_in(slot,        g_fA + (size_t)blockIdx.x * FBLKB + cnt * ACHB, ACHB, m);
            bulk_in(slot + 8192, g_wAt + cnt * WCHB,                             WCHB, m);
        } else if (cnt < NCH + 4) {
            mbar_expect_tx(m, WCHB);
            bulk_in(slot + 8192, g_w1t + (cnt - NCH) * WCHB, WCHB, m);
        } else {
            mbar_expect_tx(m, WCHB);
            bulk_in(slot + 8192, g_w2t + (cnt - NCH - 4) * WCHB, WCHB, m);
        }
    };

    if (tid == 0) { fetch(0); fetch(1); }

    float acc[2][4][4];

    // ---------- GEMM1: D1 = feat @ wA^T (19 chunks) ----------
    zero_acc(acc);
    for (int c = 0; c < NCH; ++c) {
        mbar_wait(smem_u32(&s_mb[c & 1]), (c >> 1) & 1);
        gemm1_chunk(smb + OFF_RING + (c & 1) * SLOTB, acc, mb, nb, lane);
        __syncthreads();
        if (tid == 0 && c + 2 < NCHT) fetch(c + 2);
    }

    // ---------- epilogue 1: H0 = relu(D1 + bA) ----------
    char* H0 = smem + OFF_H0;
    #pragma unroll
    for (int mt = 0; mt < 2; ++mt) {
        const int r0 = mb + mt * 16 + g;
        #pragma unroll
        for (int nt = 0; nt < 4; ++nt) {
            const int col = nb + nt * 8 + 2 * tg;
            const float bb0 = __ldg(bA + col), bb1 = __ldg(bA + col + 1);
            storeTile(H0, r0,     col, fmaxf(acc[mt][nt][0] + bb0, 0.f),
                                       fmaxf(acc[mt][nt][1] + bb1, 0.f));
            storeTile(H0, r0 + 8, col, fmaxf(acc[mt][nt][2] + bb0, 0.f),
                                       fmaxf(acc[mt][nt][3] + bb1, 0.f));
        }
    }
    __syncthreads();

    // ---------- GEMM2: D2 = h0 @ w1^T (chunks 19..22) ----------
    zero_acc(acc);
    for (int j = 0; j < 4; ++j) {
        const int cnt = NCH + j;
        mbar_wait(smem_u32(&s_mb[cnt & 1]), (cnt >> 1) & 1);
        gemm23_chunk(smb + OFF_H0, smb + OFF_RING + (cnt & 1) * SLOTB, j * 32, acc, mb, nb, lane);
        __syncthreads();
        if (tid == 0 && cnt + 2 < NCHT) fetch(cnt + 2);
    }

    // ---------- epilogue 2: T1 = relu(D2 + b1) ----------
    char* T1 = smem + OFF_T1;
    #pragma unroll
    for (int mt = 0; mt < 2; ++mt) {
        const int r0 = mb + mt * 16 + g;
        #pragma unroll
        for (int nt = 0; nt < 4; ++nt) {
            const int col = nb + nt * 8 + 2 * tg;
            const float bb0 = __ldg(b1 + col), bb1 = __ldg(b1 + col + 1);
            storeTile(T1, r0,     col, fmaxf(acc[mt][nt][0] + bb0, 0.f),
                                       fmaxf(acc[mt][nt][1] + bb1, 0.f));
            storeTile(T1, r0 + 8, col, fmaxf(acc[mt][nt][2] + bb0, 0.f),
                                       fmaxf(acc[mt][nt][3] + bb1, 0.f));
        }
    }
    __syncthreads();

    // ---------- GEMM3: D3 = t1 @ w2^T (chunks 23..26) ----------
    zero_acc(acc);
    for (int j = 0; j < 4; ++j) {
        const int cnt = NCH + 4 + j;
        mbar_wait(smem_u32(&s_mb[cnt & 1]), (cnt >> 1) & 1);
        gemm23_chunk(smb + OFF_T1, smb + OFF_RING + (cnt & 1) * SLOTB, j * 32, acc, mb, nb, lane);
        __syncthreads();
        if (tid == 0 && cnt + 2 < NCHT) fetch(cnt + 2);
    }

    // ---------- epilogue 3: F1 = relu(h0 + D3 + b2) fp32 (over ring) ----------
    {
        float* F1 = (float*)(smem + OFF_F1);
        #pragma unroll
        for (int mt = 0; mt < 2; ++mt) {
            #pragma unroll
            for (int nt = 0; nt < 4; ++nt) {
                const int col = nb + nt * 8 + 2 * tg;
                const float bb0 = __ldg(b2 + col), bb1 = __ldg(b2 + col + 1);
                #pragma unroll
                for (int half = 0; half < 2; ++half) {
                    const int r = mb + mt * 16 + g + half * 8;
                    const int off = (col >> 3) * 1024 + r * 16 + ((2 * col) & 15);
                    const uint32_t ph = *(uint32_t*)(H0 + off);
                    const uint32_t pl = *(uint32_t*)(H0 + off + 16384);
                    const float h0v = __bfloat162float(__ushort_as_bfloat16((unsigned short)(ph & 0xFFFF)))
                                    + __bfloat162float(__ushort_as_bfloat16((unsigned short)(pl & 0xFFFF)));
                    const float h1v = __bfloat162float(__ushort_as_bfloat16((unsigned short)(ph >> 16)))
                                    + __bfloat162float(__ushort_as_bfloat16((unsigned short)(pl >> 16)));
                    const float a0 = acc[mt][nt][half * 2 + 0];
                    const float a1 = acc[mt][nt][half * 2 + 1];
                    F1[r * F1ST + col]     = fmaxf(h0v + a0 + bb0, 0.f);
                    F1[r * F1ST + col + 1] = fmaxf(h1v + a1 + bb1, 0.f);
                }
            }
        }
    }
    __syncthreads();

    // ---------- wB transpose copy (over H0, now dead) ----------
    {
        float* wBs = (float*)(smem + OFF_WB);
        #pragma unroll 4
        for (int i = tid; i < 4096; i += 256) {
            const int k = i >> 5, n = i & 31;
            wBs[i] = __ldg(wB + n * 128 + k);
        }
    }
    __syncthreads();

    // ---------- stage 3: h2 = relu(h1 @ wB^T + bB) scalar fp32 ----------
    {
        const float* F1 = (const float*)(smem + OFF_F1);
        const float* wBs = (const float*)(smem + OFF_WB);
        float* F2 = (float*)(smem + OFF_F2);
        const int r  = tid >> 2;
        const int n0 = (tid & 3) * 8;
        float a3[8];
        #pragma unroll
        for (int i = 0; i < 8; ++i) a3[i] = 0.f;
        #pragma unroll 4
        for (int k = 0; k < 128; ++k) {
            const float hv = F1[r * F1ST + k];
            const float4 q0 = *(const float4*)(wBs + k * 32 + n0);
            const float4 q1 = *(const float4*)(wBs + k * 32 + n0 + 4);
            a3[0] = fmaf(hv, q0.x, a3[0]); a3[1] = fmaf(hv, q0.y, a3[1]);
            a3[2] = fmaf(hv, q0.z, a3[2]); a3[3] = fmaf(hv, q0.w, a3[3]);
            a3[4] = fmaf(hv, q1.x, a3[4]); a3[5] = fmaf(hv, q1.y, a3[5]);
            a3[6] = fmaf(hv, q1.z, a3[6]); a3[7] = fmaf(hv, q1.w, a3[7]);
        }
        #pragma unroll
        for (int n = 0; n < 8; ++n)
            F2[r * 36 + n0 + n] = fmaxf(a3[n] + __ldg(bB + n0 + n), 0.f);
    }
    __syncthreads();

    // ---------- stage 4: logits ----------
    if (tid < 128) {
        const float* F2 = (const float*)(smem + OFF_F2);
        const int r = tid >> 1, c = tid & 1;
        float s = __ldg(bC + c);
        #pragma unroll
        for (int k = 0; k < 32; ++k)
            s = fmaf(F2[r * 36 + k], __ldg(wC + c * 32 + k), s);
        out[(size_t)(row0 + r) * 2 + c] = s;
    }
}

// ---------------- launch ----------------
extern "C" void kernel_launch(void* const* d_in, const int* in_sizes, int n_in,
                              void* d_out, int out_size)
{
    const float* x      = (const float*)d_in[0];
    const float* w_step = (const float*)d_in[1];
    const float* b_step = (const float*)d_in[2];
    const float* wA     = (const float*)d_in[3];
    const float* bA     = (const float*)d_in[4];
    const float* w1     = (const float*)d_in[5];
    const float* b1     = (const float*)d_in[6];
    const float* w2     = (const float*)d_in[7];
    const float* b2     = (const float*)d_in[8];
    const float* wB     = (const float*)d_in[9];
    const float* bB     = (const float*)d_in[10];
    const float* wC     = (const float*)d_in[11];
    const float* bC     = (const float*)d_in[12];
    float* out          = (float*)d_out;

    static bool attr_set = false;
    if (!attr_set) {
        cudaFuncSetAttribute(mlp_kernel, cudaFuncAttributeMaxDynamicSharedMemorySize, SMEM_TOTAL);
        cudaFuncSetAttribute(feat_presplit_kernel, cudaFuncAttributeMaxDynamicSharedMemorySize, FSMEM);
        attr_set = true;
    }

    feat_presplit_kernel<<<FGRID + 432, 256, FSMEM>>>(x, w_step, b_step, wA, w1, w2);
    mlp_kernel<<<NCTA, 256, SMEM_TOTAL>>>(bA, b1, b2, bB, wB, wC, bC, out);
}